// round 17
// baseline (speedup 1.0000x reference)
#include <cuda_runtime.h>
#include <cuda_bf16.h>
#include <math.h>
#include <stdint.h>

// ---------------------------------------------------------------------------
// Problem dims (fixed)
// ---------------------------------------------------------------------------
#define BATCH   32
#define SEQ     512
#define DMODEL  512
#define NHEADS  8
#define HDIM    64
#define DFF     2048
#define MTOK    (BATCH * SEQ)
#define LN_EPS  1e-12f

// ---------------------------------------------------------------------------
// Scratch (device globals)
// ---------------------------------------------------------------------------
__device__ float g_t0[MTOK * DMODEL];
__device__ float g_attnln[MTOK * DMODEL];

__device__ __nv_bfloat16 g_xhi[MTOK * DMODEL];
__device__ __nv_bfloat16 g_xlo[MTOK * DMODEL];
__device__ __nv_bfloat16 g_qhi[MTOK * DMODEL];
__device__ __nv_bfloat16 g_qlo[MTOK * DMODEL];
__device__ __nv_bfloat16 g_khi[MTOK * DMODEL];
__device__ __nv_bfloat16 g_klo[MTOK * DMODEL];
__device__ __nv_bfloat16 g_vhi[MTOK * DMODEL];
__device__ __nv_bfloat16 g_vlo[MTOK * DMODEL];
__device__ __nv_bfloat16 g_chi[MTOK * DMODEL];
__device__ __nv_bfloat16 g_clo[MTOK * DMODEL];
__device__ __nv_bfloat16 g_ahi[MTOK * DMODEL];
__device__ __nv_bfloat16 g_alo[MTOK * DMODEL];
__device__ __nv_bfloat16 g_fhi[MTOK * DFF];
__device__ __nv_bfloat16 g_flo[MTOK * DFF];

__device__ __nv_bfloat16 g_wqhi[DMODEL * DMODEL];
__device__ __nv_bfloat16 g_wqlo[DMODEL * DMODEL];
__device__ __nv_bfloat16 g_wkhi[DMODEL * DMODEL];
__device__ __nv_bfloat16 g_wklo[DMODEL * DMODEL];
__device__ __nv_bfloat16 g_wvhi[DMODEL * DMODEL];
__device__ __nv_bfloat16 g_wvlo[DMODEL * DMODEL];
__device__ __nv_bfloat16 g_wohi[DMODEL * DMODEL];
__device__ __nv_bfloat16 g_wolo[DMODEL * DMODEL];
__device__ __nv_bfloat16 g_w1hi[DFF * DMODEL];
__device__ __nv_bfloat16 g_w1lo[DFF * DMODEL];
__device__ __nv_bfloat16 g_w2hi[DMODEL * DFF];
__device__ __nv_bfloat16 g_w2lo[DMODEL * DFF];

// ---------------------------------------------------------------------------
// helpers
// ---------------------------------------------------------------------------
__device__ __forceinline__ void mma16816(float* c, const uint32_t* a, const uint32_t* b)
{
    asm volatile(
        "mma.sync.aligned.m16n8k16.row.col.f32.bf16.bf16.f32 "
        "{%0,%1,%2,%3}, {%4,%5,%6,%7}, {%8,%9}, {%0,%1,%2,%3};"
        : "+f"(c[0]), "+f"(c[1]), "+f"(c[2]), "+f"(c[3])
        : "r"(a[0]), "r"(a[1]), "r"(a[2]), "r"(a[3]), "r"(b[0]), "r"(b[1]));
}

__device__ __forceinline__ void ldsm_x4(uint32_t* r, uint32_t addr)
{
    asm volatile(
        "ldmatrix.sync.aligned.m8n8.x4.shared.b16 {%0,%1,%2,%3}, [%4];"
        : "=r"(r[0]), "=r"(r[1]), "=r"(r[2]), "=r"(r[3]) : "r"(addr));
}

__device__ __forceinline__ uint32_t smem_u32(const void* p) {
    uint32_t a;
    asm("{ .reg .u64 t; cvta.to.shared.u64 t, %1; cvt.u32.u64 %0, t; }"
        : "=r"(a) : "l"(p));
    return a;
}

__device__ __forceinline__ void cp16(uint32_t dst, const void* src) {
    asm volatile("cp.async.cg.shared.global [%0], [%1], 16;"
                 :: "r"(dst), "l"(src));
}
__device__ __forceinline__ void cp_commit() {
    asm volatile("cp.async.commit_group;" ::: "memory");
}
template <int N>
__device__ __forceinline__ void cp_wait() {
    asm volatile("cp.async.wait_group %0;" :: "n"(N) : "memory");
}

__device__ __forceinline__ float fast_exp(float x) {
    float y = fmaxf(x * 1.4426950408889634f, -120.0f);
    float n = rintf(y);
    float f = y - n;
    float p = 1.3333558e-3f;
    p = fmaf(p, f, 9.6181291e-3f);
    p = fmaf(p, f, 5.5504109e-2f);
    p = fmaf(p, f, 2.4022651e-1f);
    p = fmaf(p, f, 6.9314718e-1f);
    p = fmaf(p, f, 1.0f);
    return p * __int_as_float(((int)n + 127) << 23);
}

__device__ __forceinline__ void split1(float v, unsigned short& h, unsigned short& l) {
    __nv_bfloat16 hb = __float2bfloat16_rn(v);
    float r = v - __bfloat162float(hb);
    __nv_bfloat16 lb = __float2bfloat16_rn(r);
    h = __bfloat16_as_ushort(hb);
    l = __bfloat16_as_ushort(lb);
}
__device__ __forceinline__ uint32_t pack2(unsigned short a, unsigned short b) {
    return (uint32_t)a | ((uint32_t)b << 16);
}

// per-z pointer set for batched GEMM launches
struct GPtrs {
    const __nv_bfloat16* bhi;
    const __nv_bfloat16* blo;
    const float* bias;
    float* cf;
    __nv_bfloat16* chi;
    __nv_bfloat16* clo;
};

// job table for batched weight transpose+split
struct TJob {
    const float* W;
    __nv_bfloat16* hi;
    __nv_bfloat16* lo;
    int K;
    int N;
    int tile_end;   // exclusive cumulative tile count
};
struct TJobs { TJob j[6]; };

// ---------------------------------------------------------------------------
// prep kernels
// ---------------------------------------------------------------------------
__global__ void split_kernel(const float* __restrict__ X,
                             __nv_bfloat16* __restrict__ hi,
                             __nv_bfloat16* __restrict__ lo, int n4)
{
    int i = blockIdx.x * blockDim.x + threadIdx.x;
    if (i >= n4) return;
    float4 x = ((const float4*)X)[i];
    unsigned short h0, h1, h2, h3, l0, l1, l2, l3;
    split1(x.x, h0, l0); split1(x.y, h1, l1);
    split1(x.z, h2, l2); split1(x.w, h3, l3);
    uint2 hv, lv;
    hv.x = pack2(h0, h1); hv.y = pack2(h2, h3);
    lv.x = pack2(l0, l1); lv.y = pack2(l2, l3);
    ((uint2*)hi)[i] = hv;
    ((uint2*)lo)[i] = lv;
}

// Batched transpose + split: all six weights in one launch.
// Linear tile id -> job; within job, tiles are row-major over (K/32, N/32).
__global__ void tsplit_all_kernel(TJobs jobs)
{
    __shared__ float tile[32][33];
    const int t = blockIdx.x;

    int ji = 0;
#pragma unroll
    for (int k = 0; k < 6; k++)
        if (t >= jobs.j[k].tile_end) ji = k + 1;
    const TJob& J = jobs.j[ji];
    const int base = (ji == 0) ? 0 : jobs.j[ji - 1].tile_end;
    const int local = t - base;
    const int nx = J.N / 32;
    const int n0 = (local % nx) * 32;
    const int k0 = (local / nx) * 32;
    const int K = J.K, N = J.N;

    const int tx = threadIdx.x, ty = threadIdx.y;
#pragma unroll
    for (int i = 0; i < 32; i += 8)
        tile[ty + i][tx] = J.W[(size_t)(k0 + ty + i) * N + n0 + tx];
    __syncthreads();
#pragma unroll
    for (int i = 0; i < 32; i += 8) {
        float v = tile[tx][ty + i];
        unsigned short h, l;
        split1(v, h, l);
        size_t o = (size_t)(n0 + ty + i) * K + k0 + tx;
        J.hi[o] = __ushort_as_bfloat16(h);
        J.lo[o] = __ushort_as_bfloat16(l);
    }
}

// ---------------------------------------------------------------------------
// Pipelined tensor-core split-GEMM: single-sync mainloop.
// CTA 128x64, k-tile 32, 2-stage cp.async, 60 KB smem -> 3 CTA/SM.
// blockIdx.z selects pointer set.
// ---------------------------------------------------------------------------
#define SA2 40
#define ST2_A (128 * SA2)
#define ST2_B (64 * SA2)
#define STAGE2 (2 * ST2_A + 2 * ST2_B)
#define GM_SMEM_BYTES (2 * STAGE2 * 2)

__global__ __launch_bounds__(256)
void gemm_mma(const __nv_bfloat16* __restrict__ Ahi,
              const __nv_bfloat16* __restrict__ Alo,
              GPtrs p0, GPtrs p1, GPtrs p2,
              int M, int N, int K, int do_gelu)
{
    const GPtrs& P = (blockIdx.z == 0) ? p0 : (blockIdx.z == 1) ? p1 : p2;
    const __nv_bfloat16* __restrict__ Bhi = P.bhi;
    const __nv_bfloat16* __restrict__ Blo = P.blo;
    const float* __restrict__ bias = P.bias;
    float* __restrict__ Cf = P.cf;
    __nv_bfloat16* __restrict__ Chi = P.chi;
    __nv_bfloat16* __restrict__ Clo = P.clo;

    extern __shared__ __nv_bfloat16 smb[];
    const uint32_t sm_base = smem_u32(smb);

    const int tid = threadIdx.x;
    const int wid = tid >> 5;
    const int lid = tid & 31;
    const int gID = lid >> 2;
    const int t4  = lid & 3;

    const int row0 = blockIdx.y * 128;
    const int col0 = blockIdx.x * 64;
    const int m_off = (wid & 3) * 32;
    const int n_off = (wid >> 2) * 32;

    const int a_ro = ((lid >> 3) & 1) * 8 + (lid & 7);
    const int a_ko = (lid >> 4) * 8;
    const int b_rr = lid & 7;
    const int b_ni = (lid >> 4) & 1;
    const int b_ko = ((lid >> 3) & 1) * 8;

    auto load_stage = [&](int buf, int t) {
        const int kb = t << 5;
        uint32_t base = sm_base + (uint32_t)buf * (STAGE2 * 2);
#pragma unroll
        for (int i = 0; i < 2; i++) {
            int e = tid + i * 256;
            int r = e >> 2, g = e & 3;
            uint32_t ds = (uint32_t)(r * SA2 + g * 8) * 2;
            size_t src = (size_t)(row0 + r) * K + kb + g * 8;
            cp16(base + ds, Ahi + src);
            cp16(base + ST2_A * 2 + ds, Alo + src);
        }
        {
            int r = tid >> 2, g = tid & 3;
            uint32_t ds = (uint32_t)(r * SA2 + g * 8) * 2;
            size_t src = (size_t)(col0 + r) * K + kb + g * 8;
            cp16(base + 2 * ST2_A * 2 + ds, Bhi + src);
            cp16(base + 2 * ST2_A * 2 + ST2_B * 2 + ds, Blo + src);
        }
        cp_commit();
    };

    float acc[2][4][4];
#pragma unroll
    for (int mi = 0; mi < 2; mi++)
#pragma unroll
        for (int ni = 0; ni < 4; ni++)
#pragma unroll
            for (int j = 0; j < 4; j++) acc[mi][ni][j] = 0.f;

    const int nT = K >> 5;
    load_stage(0, 0);

    for (int t = 0; t < nT; t++) {
        const int buf = t & 1;
        cp_wait<0>();          // stage t ready (only group in flight)
        __syncthreads();       // all warps done reading buffer 1-buf (iter t-1)
        if (t + 1 < nT)
            load_stage(1 - buf, t + 1);   // safe: 1-buf reads all retired

        const uint32_t sA = sm_base + (uint32_t)buf * (STAGE2 * 2);
        const uint32_t sB = sA + 2 * ST2_A * 2;

#pragma unroll
        for (int kk = 0; kk < 32; kk += 16) {
            uint32_t ahi[2][4], alo[2][4], bhi[4][2], blo[4][2];
#pragma unroll
            for (int mi = 0; mi < 2; mi++) {
                uint32_t aaddr = sA +
                    (uint32_t)((m_off + mi * 16 + a_ro) * SA2 + kk + a_ko) * 2;
                ldsm_x4(ahi[mi], aaddr);
                ldsm_x4(alo[mi], aaddr + ST2_A * 2);
            }
#pragma unroll
            for (int p = 0; p < 2; p++) {
                int n = n_off + (p * 2 + b_ni) * 8 + b_rr;
                uint32_t baddr = sB + (uint32_t)(n * SA2 + kk + b_ko) * 2;
                uint32_t r[4];
                ldsm_x4(r, baddr);
                bhi[p * 2][0] = r[0]; bhi[p * 2][1] = r[1];
                bhi[p * 2 + 1][0] = r[2]; bhi[p * 2 + 1][1] = r[3];
                ldsm_x4(r, baddr + ST2_B * 2);
                blo[p * 2][0] = r[0]; blo[p * 2][1] = r[1];
                blo[p * 2 + 1][0] = r[2]; blo[p * 2 + 1][1] = r[3];
            }
#pragma unroll
            for (int mi = 0; mi < 2; mi++)
#pragma unroll
                for (int ni = 0; ni < 4; ni++) {
                    mma16816(acc[mi][ni], ahi[mi], bhi[ni]);
                    mma16816(acc[mi][ni], alo[mi], bhi[ni]);
                    mma16816(acc[mi][ni], ahi[mi], blo[ni]);
                }
        }
    }

#pragma unroll
    for (int mi = 0; mi < 2; mi++) {
#pragma unroll
        for (int ni = 0; ni < 4; ni++) {
            int col = col0 + n_off + ni * 8 + t4 * 2;
            float b0 = bias[col], b1 = bias[col + 1];
#pragma unroll
            for (int half = 0; half < 2; half++) {
                int row = row0 + m_off + mi * 16 + gID + half * 8;
                float v0 = acc[mi][ni][half * 2 + 0] + b0;
                float v1 = acc[mi][ni][half * 2 + 1] + b1;
                if (do_gelu) {
                    v0 = 0.5f * v0 * (1.0f + erff(v0 * 0.70710678118654752f));
                    v1 = 0.5f * v1 * (1.0f + erff(v1 * 0.70710678118654752f));
                }
                size_t o = (size_t)row * N + col;
                if (Cf) {
                    float2 fo; fo.x = v0; fo.y = v1;
                    *(float2*)(Cf + o) = fo;
                }
                if (Chi) {
                    unsigned short h0, h1, l0, l1;
                    split1(v0, h0, l0);
                    split1(v1, h1, l1);
                    *(uint32_t*)(Chi + o) = pack2(h0, h1);
                    *(uint32_t*)(Clo + o) = pack2(l0, l1);
                }
            }
        }
    }
}

// ---------------------------------------------------------------------------
// Flash attention (round-16 winner, unchanged).
// ---------------------------------------------------------------------------
#define AT_SA   72
#define FQ_HI   0
#define FQ_LO   18432
#define FK0     36864
#define FMK     73728
#define FSV     139264
#define FVT     172032
#define AT_SMEM 190464

__global__ __launch_bounds__(256)
void attn_mma(const __nv_bfloat16* __restrict__ Qhi_g,
              const __nv_bfloat16* __restrict__ Qlo_g,
              const __nv_bfloat16* __restrict__ Khi_g,
              const __nv_bfloat16* __restrict__ Klo_g,
              const __nv_bfloat16* __restrict__ Vhi_g,
              const __nv_bfloat16* __restrict__ Vlo_g,
              const float* __restrict__ mask,
              __nv_bfloat16* __restrict__ Chi_g,
              __nv_bfloat16* __restrict__ Clo_g)
{
    extern __shared__ char smc[];
    const uint32_t sm_base = smem_u32(smc);

    const int tid = threadIdx.x;
    const int wid = tid >> 5, lid = tid & 31;
    const int gID = lid >> 2, t4 = lid & 3;
    const int q0 = blockIdx.x * 128;
    const int h = blockIdx.y, b = blockIdx.z;
    const size_t hb = ((size_t)b * SEQ) * DMODEL + (size_t)h * HDIM;
    const float* mbase = mask + (size_t)b * SEQ * SEQ;

    const int a_ro = ((lid >> 3) & 1) * 8 + (lid & 7);
    const int a_ko = (lid >> 4) * 8;
    const int b_rr = lid & 7;
    const int b_ni = (lid >> 4) & 1;
    const int b_ko = ((lid >> 3) & 1) * 8;

    auto load_k = [&](int bb, int kc) {
        const int k0 = kc * 64;
        uint32_t kh = sm_base + FK0 + (uint32_t)bb * 18432;
        uint32_t kl = kh + 9216;
#pragma unroll
        for (int i = 0; i < 2; i++) {
            int e = tid + i * 256;
            int r = e >> 3, g = e & 7;
            size_t src = hb + (size_t)(k0 + r) * DMODEL + g * 8;
            uint32_t ds = (uint32_t)(r * AT_SA + g * 8) * 2;
            cp16(kh + ds, Khi_g + src);
            cp16(kl + ds, Klo_g + src);
        }
        uint32_t mb = sm_base + FMK + (uint32_t)bb * 32768;
#pragma unroll
        for (int i = 0; i < 8; i++) {
            int e = tid + i * 256;
            int r = e >> 4, c4 = e & 15;
            cp16(mb + (uint32_t)(r * 64 + c4 * 4) * 4,
                 mbase + (size_t)(q0 + r) * SEQ + k0 + c4 * 4);
        }
        cp_commit();
    };

    auto stage_v = [&](int bb, int kc) {
        const int k0 = kc * 64;
        uint32_t sv = sm_base + FSV + (uint32_t)bb * 16384;
#pragma unroll
        for (int i = 0; i < 2; i++) {
            int e = tid + i * 256;
            int r = e >> 3, g = e & 7;
            size_t src = hb + (size_t)(k0 + r) * DMODEL + g * 8;
            uint32_t ds = (uint32_t)(r * 64 + g * 8) * 2;
            cp16(sv + ds, Vhi_g + src);
            cp16(sv + 8192 + ds, Vlo_g + src);
        }
        cp_commit();
    };

    load_k(0, 0);
    stage_v(0, 0);

    {
        __nv_bfloat16* Qh = (__nv_bfloat16*)(smc + FQ_HI);
        __nv_bfloat16* Ql = (__nv_bfloat16*)(smc + FQ_LO);
#pragma unroll
        for (int i = 0; i < 4; i++) {
            int e = tid + i * 256;
            int r = e >> 3, g = e & 7;
            size_t src = hb + (size_t)(q0 + r) * DMODEL + g * 8;
            int ds = r * AT_SA + g * 8;
            *(uint4*)(Qh + ds) = *(const uint4*)(Qhi_g + src);
            *(uint4*)(Ql + ds) = *(const uint4*)(Qlo_g + src);
        }
    }

    float pv[8][4];
#pragma unroll
    for (int ni = 0; ni < 8; ni++)
#pragma unroll
        for (int j = 0; j < 4; j++) pv[ni][j] = 0.f;
    float m_run[2] = {-1e30f, -1e30f};
    float l_run[2] = {0.f, 0.f};

    const uint32_t uQhi = sm_base + FQ_HI;
    const uint32_t uQlo = sm_base + FQ_LO;
    const uint32_t uVth = sm_base + FVT;
    const uint32_t uVtl = uVth + 9216;
    __nv_bfloat16* Vth = (__nv_bfloat16*)(smc + FVT);
    __nv_bfloat16* Vtl = Vth + 4608;

    for (int kc = 0; kc < 8; kc++) {
        const int bb = kc & 1;
        if (kc + 1 < 8) {
            load_k(1 - bb, kc + 1);
            stage_v(1 - bb, kc + 1);
            cp_wait<2>();
        } else {
            cp_wait<0>();
        }
        __syncthreads();

        const uint32_t uKhi = sm_base + FK0 + (uint32_t)bb * 18432;
        const uint32_t uKlo = uKhi + 9216;
        const float* msm = (const float*)(smc + FMK + (size_t)bb * 32768);

        float s[8][4];
#pragma unroll
        for (int ni = 0; ni < 8; ni++)
#pragma unroll
            for (int j = 0; j < 4; j++) s[ni][j] = 0.f;

#pragma unroll
        for (int kk = 0; kk < 64; kk += 16) {
            uint32_t ah[4], al[4];
            {
                uint32_t aaddr = (uint32_t)((wid * 16 + a_ro) * AT_SA + kk + a_ko) * 2;
                ldsm_x4(ah, uQhi + aaddr);
                ldsm_x4(al, uQlo + aaddr);
            }
#pragma unroll
            for (int p = 0; p < 4; p++) {
                int n = (p * 2 + b_ni) * 8 + b_rr;
                uint32_t baddr = (uint32_t)(n * AT_SA + kk + b_ko) * 2;
                uint32_t r[4], r2[4];
                ldsm_x4(r, uKhi + baddr);
                ldsm_x4(r2, uKlo + baddr);
                uint32_t bh0[2] = {r[0], r[1]}, bh1[2] = {r[2], r[3]};
                uint32_t bl0[2] = {r2[0], r2[1]}, bl1[2] = {r2[2], r2[3]};
                mma16816(s[p * 2], ah, bh0);
                mma16816(s[p * 2], al, bh0);
                mma16816(s[p * 2], ah, bl0);
                mma16816(s[p * 2 + 1], ah, bh1);
                mma16816(s[p * 2 + 1], al, bh1);
                mma16816(s[p * 2 + 1], ah, bl1);
            }
        }

#pragma unroll
        for (int ni = 0; ni < 8; ni++) {
            int cl = ni * 8 + t4 * 2;
#pragma unroll
            for (int hf = 0; hf < 2; hf++) {
                int row = wid * 16 + gID + hf * 8;
                float2 m2 = *(const float2*)(msm + row * 64 + cl);
                s[ni][hf * 2 + 0] = s[ni][hf * 2 + 0] * 0.125f + m2.x;
                s[ni][hf * 2 + 1] = s[ni][hf * 2 + 1] * 0.125f + m2.y;
            }
        }

        float scale0, scale1;
        {
#pragma unroll
            for (int hf = 0; hf < 2; hf++) {
                float mc = -1e30f;
#pragma unroll
                for (int ni = 0; ni < 8; ni++) {
                    mc = fmaxf(mc, fmaxf(s[ni][hf * 2], s[ni][hf * 2 + 1]));
                }
                mc = fmaxf(mc, __shfl_xor_sync(0xffffffffu, mc, 1));
                mc = fmaxf(mc, __shfl_xor_sync(0xffffffffu, mc, 2));
                float m_new = fmaxf(m_run[hf], mc);
                float sc = fast_exp(m_run[hf] - m_new);
                float sum = 0.f;
#pragma unroll
                for (int ni = 0; ni < 8; ni++) {
                    float e0 = fast_exp(s[ni][hf * 2] - m_new);
                    float e1 = fast_exp(s[ni][hf * 2 + 1] - m_new);
                    s[ni][hf * 2] = e0;
                    s[ni][hf * 2 + 1] = e1;
                    sum += e0 + e1;
                }
                sum += __shfl_xor_sync(0xffffffffu, sum, 1);
                sum += __shfl_xor_sync(0xffffffffu, sum, 2);
                l_run[hf] = l_run[hf] * sc + sum;
                m_run[hf] = m_new;
                if (hf == 0) scale0 = sc; else scale1 = sc;
            }
#pragma unroll
            for (int ni = 0; ni < 8; ni++) {
                pv[ni][0] *= scale0; pv[ni][1] *= scale0;
                pv[ni][2] *= scale1; pv[ni][3] *= scale1;
            }
        }

        uint32_t ph[4][4], pl[4][4];
#pragma unroll
        for (int c = 0; c < 4; c++) {
            unsigned short h0, h1, l0, l1;
#pragma unroll
            for (int half = 0; half < 2; half++) {
                int ni = 2 * c + half;
                split1(s[ni][0], h0, l0);
                split1(s[ni][1], h1, l1);
                ph[c][half * 2 + 0] = pack2(h0, h1);
                pl[c][half * 2 + 0] = pack2(l0, l1);
                split1(s[ni][2], h0, l0);
                split1(s[ni][3], h1, l1);
                ph[c][half * 2 + 1] = pack2(h0, h1);
                pl[c][half * 2 + 1] = pack2(l0, l1);
            }
        }

        {
            const __nv_bfloat16* Svh = (const __nv_bfloat16*)(smc + FSV + (size_t)bb * 16384);
            const __nv_bfloat16* Svl = Svh + 4096;
#pragma unroll
            for (int i = 0; i < 4; i++) {
                int e = tid + i * 256;
                int r = e >> 4, c4 = e & 15;
                uint2 hv = *(const uint2*)(Svh + r * 64 + c4 * 4);
                uint2 lv = *(const uint2*)(Svl + r * 64 + c4 * 4);
                int d = c4 * 4;
                Vth[(d + 0) * AT_SA + r] = __ushort_as_bfloat16((unsigned short)(hv.x & 0xffff));
                Vth[(d + 1) * AT_SA + r] = __ushort_as_bfloat16((unsigned short)(hv.x >> 16));
                Vth[(d + 2) * AT_SA + r] = __ushort_as_bfloat16((unsigned short)(hv.y & 0xffff));
                Vth[(d + 3) * AT_SA + r] = __ushort_as_bfloat16((unsigned short)(hv.y >> 16));
                Vtl[(d + 0) * AT_SA + r] = __ushort_as_bfloat16((unsigned short)(lv.x & 0xffff));
                Vtl[(d + 1) * AT_SA + r] = __ushort_as_bfloat16((unsigned short)(lv.x >> 16));
                Vtl[(d + 2) * AT_SA + r] = __ushort_as_bfloat16((unsigned short)(lv.y & 0xffff));
                Vtl[(d + 3) * AT_SA + r] = __ushort_as_bfloat16((unsigned short)(lv.y >> 16));
            }
        }
        __syncthreads();

#pragma unroll
        for (int c = 0; c < 4; c++) {
            int kk = c * 16;
#pragma unroll
            for (int p = 0; p < 4; p++) {
                int n = (p * 2 + b_ni) * 8 + b_rr;
                uint32_t baddr = (uint32_t)(n * AT_SA + kk + b_ko) * 2;
                uint32_t r[4], r2[4];
                ldsm_x4(r, uVth + baddr);
                ldsm_x4(r2, uVtl + baddr);
                uint32_t bh0[2] = {r[0], r[1]}, bh1[2] = {r[2], r[3]};
                uint32_t bl0[2] = {r2[0], r2[1]}, bl1[2] = {r2[2], r2[3]};
                mma16816(pv[p * 2], ph[c], bh0);
                mma16816(pv[p * 2], pl[c], bh0);
                mma16816(pv[p * 2], ph[c], bl0);
                mma16816(pv[p * 2 + 1], ph[c], bh1);
                mma16816(pv[p * 2 + 1], pl[c], bh1);
                mma16816(pv[p * 2 + 1], ph[c], bl1);
            }
        }
    }

    float is0 = 1.0f / l_run[0];
    float is1 = 1.0f / l_run[1];
#pragma unroll
    for (int ni = 0; ni < 8; ni++) {
        int d = ni * 8 + t4 * 2;
#pragma unroll
        for (int hf = 0; hf < 2; hf++) {
            int row = wid * 16 + gID + hf * 8;
            float is = (hf == 0) ? is0 : is1;
            unsigned short h0, h1, l0, l1;
            split1(pv[ni][hf * 2 + 0] * is, h0, l0);
            split1(pv[ni][hf * 2 + 1] * is, h1, l1);
            size_t o = hb + (size_t)(q0 + row) * DMODEL + d;
            *(uint32_t*)(Chi_g + o) = pack2(h0, h1);
            *(uint32_t*)(Clo_g + o) = pack2(l0, l1);
        }
    }
}

// ---------------------------------------------------------------------------
// LayerNorm + residual: warp per row (round-10 proven).
// ---------------------------------------------------------------------------
__global__ __launch_bounds__(256)
void ln_residual_kernel(const float* __restrict__ y,
                        const float* __restrict__ res,
                        const float* __restrict__ g,
                        const float* __restrict__ bta,
                        float* __restrict__ out,
                        __nv_bfloat16* __restrict__ ohi,
                        __nv_bfloat16* __restrict__ olo)
{
    const int warp = threadIdx.x >> 5;
    const int lane = threadIdx.x & 31;
    const int row  = blockIdx.x * 8 + warp;
    const size_t base = (size_t)row * DMODEL;

    float4 v[4];
    float sum = 0.f;
#pragma unroll
    for (int it = 0; it < 4; it++) {
        int c = lane * 4 + it * 128;
        float4 a = *(const float4*)(y + base + c);
        float4 bb = *(const float4*)(res + base + c);
        v[it].x = a.x + bb.x; v[it].y = a.y + bb.y;
        v[it].z = a.z + bb.z; v[it].w = a.w + bb.w;
        sum += v[it].x + v[it].y + v[it].z + v[it].w;
    }
#pragma unroll
    for (int off = 16; off; off >>= 1)
        sum += __shfl_xor_sync(0xffffffffu, sum, off);
    float mean = sum * (1.0f / 512.0f);

    float var = 0.f;
#pragma unroll
    for (int it = 0; it < 4; it++) {
        v[it].x -= mean; v[it].y -= mean; v[it].z -= mean; v[it].w -= mean;
        var += v[it].x * v[it].x + v[it].y * v[it].y
             + v[it].z * v[it].z + v[it].w * v[it].w;
    }
#pragma unroll
    for (int off = 16; off; off >>= 1)
        var += __shfl_xor_sync(0xffffffffu, var, off);
    float inv = rsqrtf(var * (1.0f / 512.0f) + LN_EPS);

#pragma unroll
    for (int it = 0; it < 4; it++) {
        int c = lane * 4 + it * 128;
        float4 gg = *(const float4*)(g + c);
        float4 bb = *(const float4*)(bta + c);
        float4 o;
        o.x = v[it].x * inv * gg.x + bb.x;
        o.y = v[it].y * inv * gg.y + bb.y;
        o.z = v[it].z * inv * gg.z + bb.z;
        o.w = v[it].w * inv * gg.w + bb.w;
        *(float4*)(out + base + c) = o;
        if (ohi) {
            unsigned short h0, h1, h2, h3, l0, l1, l2, l3;
            split1(o.x, h0, l0); split1(o.y, h1, l1);
            split1(o.z, h2, l2); split1(o.w, h3, l3);
            uint2 hv, lv;
            hv.x = pack2(h0, h1); hv.y = pack2(h2, h3);
            lv.x = pack2(l0, l1); lv.y = pack2(l2, l3);
            *(uint2*)(ohi + base + c) = hv;
            *(uint2*)(olo + base + c) = lv;
        }
    }
}

// ---------------------------------------------------------------------------
// launch
// ---------------------------------------------------------------------------
extern "C" void kernel_launch(void* const* d_in, const int* in_sizes, int n_in,
                              void* d_out, int out_size)
{
    const float* x     = (const float*)d_in[0];
    const float* mask  = (const float*)d_in[1];
    const float* Wq    = (const float*)d_in[2];
    const float* bq    = (const float*)d_in[3];
    const float* Wk    = (const float*)d_in[4];
    const float* bk    = (const float*)d_in[5];
    const float* Wv    = (const float*)d_in[6];
    const float* bv    = (const float*)d_in[7];
    const float* Wo    = (const float*)d_in[8];
    const float* bo    = (const float*)d_in[9];
    const float* ln1g  = (const float*)d_in[10];
    const float* ln1b  = (const float*)d_in[11];
    const float* W1    = (const float*)d_in[12];
    const float* b1    = (const float*)d_in[13];
    const float* W2    = (const float*)d_in[14];
    const float* b2    = (const float*)d_in[15];
    const float* ln2g  = (const float*)d_in[16];
    const float* ln2b  = (const float*)d_in[17];
    float* out = (float*)d_out;

    float *t0, *aln;
    cudaGetSymbolAddress((void**)&t0,  g_t0);
    cudaGetSymbolAddress((void**)&aln, g_attnln);

    __nv_bfloat16 *xhi, *xlo, *qhi, *qlo, *khi, *klo, *vhi, *vlo;
    __nv_bfloat16 *chi, *clo, *ahi, *alo, *fhi, *flo;
    cudaGetSymbolAddress((void**)&xhi, g_xhi);
    cudaGetSymbolAddress((void**)&xlo, g_xlo);
    cudaGetSymbolAddress((void**)&qhi, g_qhi);
    cudaGetSymbolAddress((void**)&qlo, g_qlo);
    cudaGetSymbolAddress((void**)&khi, g_khi);
    cudaGetSymbolAddress((void**)&klo, g_klo);
    cudaGetSymbolAddress((void**)&vhi, g_vhi);
    cudaGetSymbolAddress((void**)&vlo, g_vlo);
    cudaGetSymbolAddress((void**)&chi, g_chi);
    cudaGetSymbolAddress((void**)&clo, g_clo);
    cudaGetSymbolAddress((void**)&ahi, g_ahi);
    cudaGetSymbolAddress((void**)&alo, g_alo);
    cudaGetSymbolAddress((void**)&fhi, g_fhi);
    cudaGetSymbolAddress((void**)&flo, g_flo);

    __nv_bfloat16 *wqh, *wql, *wkh, *wkl, *wvh, *wvl, *woh, *wol, *w1h, *w1l, *w2h, *w2l;
    cudaGetSymbolAddress((void**)&wqh, g_wqhi);
    cudaGetSymbolAddress((void**)&wql, g_wqlo);
    cudaGetSymbolAddress((void**)&wkh, g_wkhi);
    cudaGetSymbolAddress((void**)&wkl, g_wklo);
    cudaGetSymbolAddress((void**)&wvh, g_wvhi);
    cudaGetSymbolAddress((void**)&wvl, g_wvlo);
    cudaGetSymbolAddress((void**)&woh, g_wohi);
    cudaGetSymbolAddress((void**)&wol, g_wolo);
    cudaGetSymbolAddress((void**)&w1h, g_w1hi);
    cudaGetSymbolAddress((void**)&w1l, g_w1lo);
    cudaGetSymbolAddress((void**)&w2h, g_w2hi);
    cudaGetSymbolAddress((void**)&w2l, g_w2lo);

    cudaFuncSetAttribute(attn_mma,
                         cudaFuncAttributeMaxDynamicSharedMemorySize, AT_SMEM);
    cudaFuncSetAttribute(gemm_mma,
                         cudaFuncAttributeMaxDynamicSharedMemorySize, GM_SMEM_BYTES);

    // batched weight transpose + split: one launch, 3072 tiles
    {
        TJobs jobs;
        jobs.j[0] = {Wq, wqh, wql, DMODEL, DMODEL, 256};
        jobs.j[1] = {Wk, wkh, wkl, DMODEL, DMODEL, 512};
        jobs.j[2] = {Wv, wvh, wvl, DMODEL, DMODEL, 768};
        jobs.j[3] = {Wo, woh, wol, DMODEL, DMODEL, 1024};
        jobs.j[4] = {W1, w1h, w1l, DMODEL, DFF, 2048};
        jobs.j[5] = {W2, w2h, w2l, DFF, DMODEL, 3072};
        tsplit_all_kernel<<<3072, dim3(32, 8)>>>(jobs);
    }

    // split input x
    {
        int n4 = MTOK * DMODEL / 4;
        split_kernel<<<(n4 + 255) / 256, 256>>>(x, xhi, xlo, n4);
    }

    // QKV projections: one z=3 batched launch
    {
        GPtrs pq = {wqh, wql, bq, nullptr, qhi, qlo};
        GPtrs pk = {wkh, wkl, bk, nullptr, khi, klo};
        GPtrs pv = {wvh, wvl, bv, nullptr, vhi, vlo};
        dim3 grid(DMODEL / 64, MTOK / 128, 3);
        gemm_mma<<<grid, 256, GM_SMEM_BYTES>>>(xhi, xlo, pq, pk, pv,
                                               MTOK, DMODEL, DMODEL, 0);
    }

    // flash attention -> ctx bf16 hi/lo
    {
        dim3 grid(SEQ / 128, NHEADS, BATCH);
        attn_mma<<<grid, 256, AT_SMEM>>>(qhi, qlo, khi, klo, vhi, vlo,
                                         mask, chi, clo);
    }

    // output projection + residual LN
    {
        GPtrs po = {woh, wol, bo, t0, nullptr, nullptr};
        dim3 grid(DMODEL / 64, MTOK / 128, 1);
        gemm_mma<<<grid, 256, GM_SMEM_BYTES>>>(chi, clo, po, po, po,
                                               MTOK, DMODEL, DMODEL, 0);
        ln_residual_kernel<<<MTOK / 8, 256>>>(t0, x, ln1g, ln1b, aln, ahi, alo);
    }

    // FFN
    {
        GPtrs p1 = {w1h, w1l, b1, nullptr, fhi, flo};
        dim3 grid1(DFF / 64, MTOK / 128, 1);
        gemm_mma<<<grid1, 256, GM_SMEM_BYTES>>>(ahi, alo, p1, p1, p1,
                                                MTOK, DFF, DMODEL, 1);
        GPtrs p2 = {w2h, w2l, b2, t0, nullptr, nullptr};
        dim3 grid2(DMODEL / 64, MTOK / 128, 1);
        gemm_mma<<<grid2, 256, GM_SMEM_BYTES>>>(fhi, flo, p2, p2, p2,
                                                MTOK, DMODEL, DFF, 0);
        ln_residual_kernel<<<MTOK / 8, 256>>>(t0, aln, ln2g, ln2b, out,
                                              nullptr, nullptr);
    }
}